// round 6
// baseline (speedup 1.0000x reference)
#include <cuda_runtime.h>
#include <math.h>

// Problem constants (fixed shapes per reference)
#define V  4
#define T  4
#define NS 100000
#define NH 12288
#define E  100000
#define H  64
#define C  (V*T)          // 16 (v, t') edge-type combos
#define NEG 0.01f

// ---------------- scratch (__device__ globals; no allocation allowed) ----------------
__device__ int    g_deg_out[C*NS];        // out-degree per (combo, src-node)   6.4 MB
__device__ int    g_deg_in [C*NH];        // in-degree  per (combo, dst-node)   0.8 MB
__device__ int    g_cursor [C*NH];        // sort cursors                       0.8 MB
__device__ int    g_off    [C*(NH+1)];    // CSR offsets                        0.8 MB
__device__ float4 g_xT     [V*NS];        // x transposed: [v][n][t0..t3]       6.4 MB
__device__ float2 g_sorted [C*E];         // {norm_src, bitcast(xT index)}     12.8 MB
__device__ float  g_s      [C*T*NH];      // s[v][t'][t][nh]                    3.0 MB

__device__ __forceinline__ float fixnum(float a) {
    if (isnan(a)) return 0.0f;
    if (isinf(a)) return a > 0.0f ? 3.4028234663852886e38f : -3.4028234663852886e38f;
    return a;
}

// ---------------- K0: zero the counters ----------------
__global__ void k_zero() {
    int i = blockIdx.x * blockDim.x + threadIdx.x;
    int stride = gridDim.x * blockDim.x;
    for (int j = i; j < C*NS; j += stride) g_deg_out[j] = 0;
    for (int j = i; j < C*NH; j += stride) { g_deg_in[j] = 0; g_cursor[j] = 0; }
}

// ---------------- K1: transpose x -> xT (nan_to_num folded in) ----------------
__global__ void k_prep(const float* __restrict__ x) {
    int i = blockIdx.x * blockDim.x + threadIdx.x;
    if (i >= V*NS) return;
    int v = i / NS, n = i - v*NS;
    float4 r;
    r.x = fixnum(x[(v*T + 0)*NS + n]);
    r.y = fixnum(x[(v*T + 1)*NS + n]);
    r.z = fixnum(x[(v*T + 2)*NS + n]);
    r.w = fixnum(x[(v*T + 3)*NS + n]);
    g_xT[i] = r;
}

// ---------------- K2: degree counts (int atomics, spread addresses) ----------------
__global__ void k_deg(const int* __restrict__ src, const int* __restrict__ dst) {
    int i = blockIdx.x * blockDim.x + threadIdx.x;
    if (i >= C*E) return;
    int c = i / E;
    atomicAdd(&g_deg_out[c*NS + src[i]], 1);
    atomicAdd(&g_deg_in [c*NH + dst[i]], 1);
}

// ---------------- K3: per-combo exclusive scan of deg_in (NH=12288 = 1024*12) ----------------
__global__ void k_scan() {
    int c   = blockIdx.x;
    int tid = threadIdx.x;
    const int* deg = g_deg_in + c*NH;
    int*       off = g_off    + c*(NH+1);

    int vals[12];
    int base = tid * 12;
    int sum = 0;
#pragma unroll
    for (int k = 0; k < 12; k++) { vals[k] = deg[base + k]; sum += vals[k]; }

    __shared__ int ssum[1024];
    ssum[tid] = sum;
    __syncthreads();
    // Hillis-Steele inclusive scan over 1024 thread sums
    for (int d = 1; d < 1024; d <<= 1) {
        int t = 0;
        if (tid >= d) t = ssum[tid - d];
        __syncthreads();
        if (tid >= d) ssum[tid] += t;
        __syncthreads();
    }
    int run = ssum[tid] - sum;   // exclusive prefix for this thread's chunk
#pragma unroll
    for (int k = 0; k < 12; k++) { off[base + k] = run; run += vals[k]; }
    if (tid == 1023) off[NH] = run;   // == E
}

// ---------------- K4: counting-sort edges by dst; pre-fold norm_src ----------------
__global__ void k_sort(const int* __restrict__ src, const int* __restrict__ dst) {
    int i = blockIdx.x * blockDim.x + threadIdx.x;
    if (i >= C*E) return;
    int c = i / E;
    int s = src[i];
    int d = dst[i];
    int pos = g_off[c*(NH+1) + d] + atomicAdd(&g_cursor[c*NH + d], 1);
    float norm = rsqrtf(fmaxf((float)g_deg_out[c*NS + s], 1.0f));
    float2 ent;
    ent.x = norm;
    ent.y = __int_as_float((c >> 2) * NS + s);   // v*NS + src: direct xT index
    g_sorted[c*E + pos] = ent;
}

// ---------------- K5: atomic-free accumulation: thread = one (combo, dst node) ----------------
__global__ void __launch_bounds__(256) k_accum() {
    int i = blockIdx.x * blockDim.x + threadIdx.x;
    if (i >= C*NH) return;
    int c = i / NH, n = i - c*NH;
    int start = g_off[c*(NH+1) + n];
    int end   = g_off[c*(NH+1) + n + 1];

    float4 acc = make_float4(0.f, 0.f, 0.f, 0.f);
    const float2* __restrict__ srt = g_sorted + (long)c * E;
    for (int e = start; e < end; e++) {
        float2 ent = srt[e];
        float4 xv  = g_xT[__float_as_int(ent.y)];
        acc.x = fmaf(xv.x, ent.x, acc.x);
        acc.y = fmaf(xv.y, ent.x, acc.y);
        acc.z = fmaf(xv.z, ent.x, acc.z);
        acc.w = fmaf(xv.w, ent.x, acc.w);
    }
    float nd = rsqrtf(fmaxf((float)(end - start), 1.0f));
    int base = c * T * NH + n;                 // s[c][t][n], t-stride = NH
    g_s[base + 0*NH] = acc.x * nd;
    g_s[base + 1*NH] = acc.y * nd;
    g_s[base + 2*NH] = acc.z * nd;
    g_s[base + 3*NH] = acc.w * nd;
}

// ---------------- K6: epilogue  out[nh,v,t,h] = sum_{t'} lrelu(s*W + b) ----------------
// grid: (NH/64, V*T), block 256
__global__ void __launch_bounds__(256) k_epi(const float* __restrict__ Wp,
                                             const float* __restrict__ Bp,
                                             float* __restrict__ out) {
    int vt = blockIdx.y;            // v*T + t
    int v  = vt >> 2;
    int t  = vt & 3;
    int tid = threadIdx.x;

    __shared__ float sW[T*H];       // [t'][h], 256
    __shared__ float sB[T*H];
    __shared__ float ss[T*64];      // [t'][nh_local], 256
    sW[tid] = Wp[v*(T*H) + tid];
    sB[tid] = Bp[v*(T*H) + tid];
    {
        int tp = tid >> 6;          // 0..3
        int nl = tid & 63;          // 0..63
        ss[tid] = g_s[((v*T + tp)*T + t)*NH + blockIdx.x*64 + nl];
    }
    __syncthreads();

    int hq  = tid & 15;             // h-quad: h = hq*4 .. hq*4+3
    int row = tid >> 4;             // 0..15
#pragma unroll
    for (int j = 0; j < 4; j++) {
        int nl = row + 16*j;
        int nh = blockIdx.x*64 + nl;
        float4 acc = make_float4(0.f, 0.f, 0.f, 0.f);
#pragma unroll
        for (int p = 0; p < 4; p++) {
            float sv = ss[p*64 + nl];
#pragma unroll
            for (int k = 0; k < 4; k++) {
                int h = hq*4 + k;
                float y = fmaf(sv, sW[p*H + h], sB[p*H + h]);
                y = (y >= 0.0f) ? y : NEG * y;
                (&acc.x)[k] += y;
            }
        }
        // out index: ((nh*V + v)*T + t)*H + hq*4  -> float4 slot (nh*16 + vt)*16 + hq
        reinterpret_cast<float4*>(out)[(nh*16 + vt)*16 + hq] = acc;
    }
}

// ---------------- launcher ----------------
extern "C" void kernel_launch(void* const* d_in, const int* in_sizes, int n_in,
                              void* d_out, int out_size) {
    const float* x   = (const float*)d_in[0];   // [V,T,NS]
    const float* Wp  = (const float*)d_in[1];   // [V,T,H]
    const float* Bp  = (const float*)d_in[2];   // [V,T,H]
    const int*   src = (const int*)  d_in[3];   // [V,T,E]
    const int*   dst = (const int*)  d_in[4];   // [V,T,E]
    float* out = (float*)d_out;                 // [NH,V,T,H]
    (void)in_sizes; (void)n_in; (void)out_size;

    k_zero<<<1600, 1024>>>();
    k_prep<<<(V*NS + 255)/256, 256>>>(x);
    k_deg <<<(C*E + 255)/256, 256>>>(src, dst);
    k_scan<<<C, 1024>>>();
    k_sort<<<(C*E + 255)/256, 256>>>(src, dst);
    k_accum<<<(C*NH + 255)/256, 256>>>();
    k_epi <<<dim3(NH/64, V*T), 256>>>(Wp, Bp, out);
}

// round 7
// speedup vs baseline: 1.1532x; 1.1532x over previous
#include <cuda_runtime.h>
#include <math.h>

// Problem constants (fixed shapes per reference)
#define V  4
#define T  4
#define NS 100000
#define NH 12288
#define E  100000
#define H  64
#define C  (V*T)          // 16 (v, t') edge-type combos
#define NEG 0.01f

// ---------------- scratch (__device__ globals; no allocation allowed) ----------------
__device__ int    g_deg_out[C*NS];        // out-degree per (combo, src-node)   6.4 MB
__device__ int    g_deg_in [C*NH];        // in-degree  per (combo, dst-node)   0.8 MB
__device__ float4 g_xT     [V*NS];        // x transposed: [v][n][t0..t3]       6.4 MB
__device__ float  g_s      [C*T*NH];      // s[v][t'][t][nh]                    3.0 MB

__device__ __forceinline__ float fixnum(float a) {
    if (isnan(a)) return 0.0f;
    if (isinf(a)) return a > 0.0f ? 3.4028234663852886e38f : -3.4028234663852886e38f;
    return a;
}

// ---------------- K1: fused zero (deg_out, deg_in, g_s) + transpose x -> xT ----------------
__global__ void k_init(const float* __restrict__ x) {
    int tid0   = blockIdx.x * blockDim.x + threadIdx.x;
    int stride = gridDim.x * blockDim.x;

    const int4   z4 = make_int4(0, 0, 0, 0);
    const float4 zf = make_float4(0.f, 0.f, 0.f, 0.f);

    // zero deg_out: C*NS = 1,600,000 ints -> 400,000 int4
    for (int j = tid0; j < C*NS/4; j += stride)
        reinterpret_cast<int4*>(g_deg_out)[j] = z4;
    // zero deg_in: C*NH = 196,608 ints -> 49,152 int4
    for (int j = tid0; j < C*NH/4; j += stride)
        reinterpret_cast<int4*>(g_deg_in)[j] = z4;
    // zero g_s: C*T*NH = 786,432 floats -> 196,608 float4
    for (int j = tid0; j < C*T*NH/4; j += stride)
        reinterpret_cast<float4*>(g_s)[j] = zf;

    // transpose x (nan_to_num folded): xT[v][n] = {x[v,0,n], x[v,1,n], x[v,2,n], x[v,3,n]}
    for (int j = tid0; j < V*NS; j += stride) {
        int v = j / NS, n = j - v*NS;
        float4 r;
        r.x = fixnum(x[(v*T + 0)*NS + n]);
        r.y = fixnum(x[(v*T + 1)*NS + n]);
        r.z = fixnum(x[(v*T + 2)*NS + n]);
        r.w = fixnum(x[(v*T + 3)*NS + n]);
        g_xT[j] = r;
    }
}

// ---------------- K2: degree counts (int atomics, int4-vectorized edge reads) ----------------
// thread = 4 consecutive edges of one combo (E % 4 == 0 so quads never straddle combos)
__global__ void k_deg(const int4* __restrict__ src4, const int4* __restrict__ dst4) {
    int i = blockIdx.x * blockDim.x + threadIdx.x;
    if (i >= C*E/4) return;
    int c = i / (E/4);
    int4 s = src4[i];
    int4 d = dst4[i];
    int* dout = g_deg_out + c*NS;
    int* din  = g_deg_in  + c*NH;
    atomicAdd(&dout[s.x], 1); atomicAdd(&dout[s.y], 1);
    atomicAdd(&dout[s.z], 1); atomicAdd(&dout[s.w], 1);
    atomicAdd(&din [d.x], 1); atomicAdd(&din [d.y], 1);
    atomicAdd(&din [d.z], 1); atomicAdd(&din [d.w], 1);
}

// ---------------- K3: direct scatter with norm_src folded (float atomics into g_s) ----------------
__global__ void __launch_bounds__(256) k_scatter(const int4* __restrict__ src4,
                                                 const int4* __restrict__ dst4) {
    int i = blockIdx.x * blockDim.x + threadIdx.x;
    if (i >= C*E/4) return;
    int c = i / (E/4);
    int v = c >> 2;
    int4 sq = src4[i];
    int4 dq = dst4[i];
    int ssv[4] = {sq.x, sq.y, sq.z, sq.w};
    int ddv[4] = {dq.x, dq.y, dq.z, dq.w};

    const int*    dout = g_deg_out + c*NS;
    const float4* xT   = g_xT      + v*NS;
    float*        sc   = g_s       + c*T*NH;   // [t][n], t-stride NH

#pragma unroll
    for (int k = 0; k < 4; k++) {
        int s = ssv[k];
        int d = ddv[k];
        float nrm = rsqrtf(fmaxf((float)dout[s], 1.0f));
        float4 xv = xT[s];
        atomicAdd(sc + 0*NH + d, xv.x * nrm);
        atomicAdd(sc + 1*NH + d, xv.y * nrm);
        atomicAdd(sc + 2*NH + d, xv.z * nrm);
        atomicAdd(sc + 3*NH + d, xv.w * nrm);
    }
}

// ---------------- K4: epilogue  out[nh,v,t,h] = sum_{t'} lrelu(s*norm_dst*W + b) ----------------
// grid: (NH/64, V*T), block 256; norm_dst folded into the ss load
__global__ void __launch_bounds__(256) k_epi(const float* __restrict__ Wp,
                                             const float* __restrict__ Bp,
                                             float* __restrict__ out) {
    int vt = blockIdx.y;            // v*T + t
    int v  = vt >> 2;
    int t  = vt & 3;
    int tid = threadIdx.x;

    __shared__ float sW[T*H];       // [t'][h], 256
    __shared__ float sB[T*H];
    __shared__ float ss[T*64];      // [t'][nh_local], 256
    sW[tid] = Wp[v*(T*H) + tid];
    sB[tid] = Bp[v*(T*H) + tid];
    {
        int tp = tid >> 6;          // 0..3  (edge-type t')
        int nl = tid & 63;          // 0..63
        int nh = blockIdx.x*64 + nl;
        int cc = v*T + tp;          // combo
        float nd = rsqrtf(fmaxf((float)g_deg_in[cc*NH + nh], 1.0f));
        ss[tid] = g_s[(cc*T + t)*NH + nh] * nd;
    }
    __syncthreads();

    int hq  = tid & 15;             // h-quad: h = hq*4 .. hq*4+3
    int row = tid >> 4;             // 0..15
#pragma unroll
    for (int j = 0; j < 4; j++) {
        int nl = row + 16*j;
        int nh = blockIdx.x*64 + nl;
        float4 acc = make_float4(0.f, 0.f, 0.f, 0.f);
#pragma unroll
        for (int p = 0; p < 4; p++) {
            float sv = ss[p*64 + nl];
#pragma unroll
            for (int k = 0; k < 4; k++) {
                int h = hq*4 + k;
                float y = fmaf(sv, sW[p*H + h], sB[p*H + h]);
                y = (y >= 0.0f) ? y : NEG * y;
                (&acc.x)[k] += y;
            }
        }
        // out index: ((nh*V + v)*T + t)*H + hq*4  -> float4 slot (nh*16 + vt)*16 + hq
        reinterpret_cast<float4*>(out)[(nh*16 + vt)*16 + hq] = acc;
    }
}

// ---------------- launcher ----------------
extern "C" void kernel_launch(void* const* d_in, const int* in_sizes, int n_in,
                              void* d_out, int out_size) {
    const float* x   = (const float*)d_in[0];   // [V,T,NS]
    const float* Wp  = (const float*)d_in[1];   // [V,T,H]
    const float* Bp  = (const float*)d_in[2];   // [V,T,H]
    const int*   src = (const int*)  d_in[3];   // [V,T,E]
    const int*   dst = (const int*)  d_in[4];   // [V,T,E]
    float* out = (float*)d_out;                 // [NH,V,T,H]
    (void)in_sizes; (void)n_in; (void)out_size;

    const int QUADS = C*E/4;                    // 400,000

    k_init   <<<1024, 256>>>(x);
    k_deg    <<<(QUADS + 255)/256, 256>>>((const int4*)src, (const int4*)dst);
    k_scatter<<<(QUADS + 255)/256, 256>>>((const int4*)src, (const int4*)dst);
    k_epi    <<<dim3(NH/64, V*T), 256>>>(Wp, Bp, out);
}

// round 8
// speedup vs baseline: 1.5284x; 1.3254x over previous
#include <cuda_runtime.h>
#include <math.h>

// Problem constants (fixed shapes per reference)
#define V  4
#define T  4
#define NS 100000
#define NH 12288
#define E  100000
#define H  64
#define C  (V*T)          // 16 (v, t') edge-type combos
#define NEG 0.01f

// ---------------- scratch (__device__ globals; no allocation allowed) ----------------
__device__ int    g_deg_out[C*NS];        // out-degree per (combo, src-node)   6.4 MB
__device__ int    g_deg_in [C*NH];        // in-degree  per (combo, dst-node)   0.8 MB
__device__ float4 g_xn     [C*NS];        // normalized features per combo:    25.6 MB
                                          //   xn[c][s] = {x[v,t,s]*norm_src}_t
__device__ float4 g_s4     [C*NH];        // s accumulators, t in components    3.0 MB

__device__ __forceinline__ float fixnum(float a) {
    if (isnan(a)) return 0.0f;
    if (isinf(a)) return a > 0.0f ? 3.4028234663852886e38f : -3.4028234663852886e38f;
    return a;
}

__device__ __forceinline__ void red_add_v4(float4* addr, float a, float b, float c, float d) {
    asm volatile("red.global.add.v4.f32 [%0], {%1, %2, %3, %4};"
                 :: "l"(addr), "f"(a), "f"(b), "f"(c), "f"(d) : "memory");
}

// ---------------- K1: zero all accumulators (grid-stride, 16B stores) ----------------
__global__ void k_init() {
    int tid0   = blockIdx.x * blockDim.x + threadIdx.x;
    int stride = gridDim.x * blockDim.x;
    const int4   z4 = make_int4(0, 0, 0, 0);
    const float4 zf = make_float4(0.f, 0.f, 0.f, 0.f);
    for (int j = tid0; j < C*NS/4; j += stride)
        reinterpret_cast<int4*>(g_deg_out)[j] = z4;
    for (int j = tid0; j < C*NH/4; j += stride)
        reinterpret_cast<int4*>(g_deg_in)[j] = z4;
    for (int j = tid0; j < C*NH; j += stride)
        g_s4[j] = zf;
}

// ---------------- K2: degree counts (int REDs, int4-vectorized edge reads) ----------------
// thread = 4 consecutive edges of one combo (E % 4 == 0 so quads never straddle combos)
__global__ void k_deg(const int4* __restrict__ src4, const int4* __restrict__ dst4) {
    int i = blockIdx.x * blockDim.x + threadIdx.x;
    if (i >= C*E/4) return;
    int c = i / (E/4);
    int4 s = src4[i];
    int4 d = dst4[i];
    int* dout = g_deg_out + c*NS;
    int* din  = g_deg_in  + c*NH;
    atomicAdd(&dout[s.x], 1); atomicAdd(&dout[s.y], 1);
    atomicAdd(&dout[s.z], 1); atomicAdd(&dout[s.w], 1);
    atomicAdd(&din [d.x], 1); atomicAdd(&din [d.y], 1);
    atomicAdd(&din [d.z], 1); atomicAdd(&din [d.w], 1);
}

// ---------------- K3: build normalized features  xn[c][s] = fix(x[v,:,s]) * rsqrt(deg_out) ----------------
// Fully coalesced streams: consecutive threads -> consecutive s.
__global__ void k_xn(const float* __restrict__ x) {
    int i = blockIdx.x * blockDim.x + threadIdx.x;
    if (i >= C*NS) return;
    int c = i / NS, s = i - c*NS;
    int v = c >> 2;
    float nrm = rsqrtf(fmaxf((float)g_deg_out[i], 1.0f));
    float4 r;
    r.x = fixnum(x[(v*T + 0)*NS + s]) * nrm;
    r.y = fixnum(x[(v*T + 1)*NS + s]) * nrm;
    r.z = fixnum(x[(v*T + 2)*NS + s]) * nrm;
    r.w = fixnum(x[(v*T + 3)*NS + s]) * nrm;
    g_xn[i] = r;
}

// ---------------- K4: scatter — one 16B gather + one v4 RED per edge ----------------
__global__ void __launch_bounds__(256) k_scatter(const int4* __restrict__ src4,
                                                 const int4* __restrict__ dst4) {
    int i = blockIdx.x * blockDim.x + threadIdx.x;
    if (i >= C*E/4) return;
    int c = i / (E/4);
    int4 sq = src4[i];
    int4 dq = dst4[i];

    const float4* __restrict__ xn = g_xn + c*NS;
    float4*                    sc = g_s4 + c*NH;

    // issue all 4 gathers first (independent chains -> MLP=4)
    float4 x0 = xn[sq.x];
    float4 x1 = xn[sq.y];
    float4 x2 = xn[sq.z];
    float4 x3 = xn[sq.w];
    red_add_v4(&sc[dq.x], x0.x, x0.y, x0.z, x0.w);
    red_add_v4(&sc[dq.y], x1.x, x1.y, x1.z, x1.w);
    red_add_v4(&sc[dq.z], x2.x, x2.y, x2.z, x2.w);
    red_add_v4(&sc[dq.w], x3.x, x3.y, x3.z, x3.w);
}

// ---------------- K5: epilogue  out[nh,v,t,h] = sum_{t'} lrelu(s*norm_dst*W + b) ----------------
// grid: (NH/64, V*T), block 256; W/B register-hoisted, norm_dst folded at the ss load
__global__ void __launch_bounds__(256) k_epi(const float* __restrict__ Wp,
                                             const float* __restrict__ Bp,
                                             float* __restrict__ out) {
    int vt = blockIdx.y;            // v*T + t
    int v  = vt >> 2;
    int t  = vt & 3;
    int tid = threadIdx.x;

    __shared__ float sW[T*H];       // [t'][h], 256
    __shared__ float sB[T*H];
    __shared__ float ss[T*64];      // [t'][nh_local], 256
    sW[tid] = Wp[v*(T*H) + tid];
    sB[tid] = Bp[v*(T*H) + tid];
    {
        int tp = tid >> 6;          // 0..3  (edge-type t')
        int nl = tid & 63;          // 0..63
        int nh = blockIdx.x*64 + nl;
        int cc = v*T + tp;          // combo
        float nd = rsqrtf(fmaxf((float)g_deg_in[cc*NH + nh], 1.0f));
        ss[tid] = reinterpret_cast<const float*>(g_s4 + (cc*NH + nh))[t] * nd;
    }
    __syncthreads();

    int hq  = tid & 15;             // h-quad: h = hq*4 .. hq*4+3
    int row = tid >> 4;             // 0..15

    // hoist W/B for this thread's 4 h-values x 4 t' into registers (one LDS each)
    float wr[16], br[16];
#pragma unroll
    for (int p = 0; p < 4; p++)
#pragma unroll
        for (int k = 0; k < 4; k++) {
            wr[p*4 + k] = sW[p*H + hq*4 + k];
            br[p*4 + k] = sB[p*H + hq*4 + k];
        }

#pragma unroll
    for (int j = 0; j < 4; j++) {
        int nl = row + 16*j;
        int nh = blockIdx.x*64 + nl;
        float4 acc = make_float4(0.f, 0.f, 0.f, 0.f);
#pragma unroll
        for (int p = 0; p < 4; p++) {
            float sv = ss[p*64 + nl];
#pragma unroll
            for (int k = 0; k < 4; k++) {
                float y = fmaf(sv, wr[p*4 + k], br[p*4 + k]);
                y = fmaxf(y, NEG * y);        // leaky relu (NEG < 1)
                (&acc.x)[k] += y;
            }
        }
        // out index: ((nh*V + v)*T + t)*H + hq*4  -> float4 slot (nh*16 + vt)*16 + hq
        reinterpret_cast<float4*>(out)[(nh*16 + vt)*16 + hq] = acc;
    }
}

// ---------------- launcher ----------------
extern "C" void kernel_launch(void* const* d_in, const int* in_sizes, int n_in,
                              void* d_out, int out_size) {
    const float* x   = (const float*)d_in[0];   // [V,T,NS]
    const float* Wp  = (const float*)d_in[1];   // [V,T,H]
    const float* Bp  = (const float*)d_in[2];   // [V,T,H]
    const int*   src = (const int*)  d_in[3];   // [V,T,E]
    const int*   dst = (const int*)  d_in[4];   // [V,T,E]
    float* out = (float*)d_out;                 // [NH,V,T,H]
    (void)in_sizes; (void)n_in; (void)out_size;

    const int QUADS = C*E/4;                    // 400,000

    k_init   <<<592, 256>>>();
    k_deg    <<<(QUADS + 255)/256, 256>>>((const int4*)src, (const int4*)dst);
    k_xn     <<<(C*NS + 255)/256, 256>>>(x);
    k_scatter<<<(QUADS + 255)/256, 256>>>((const int4*)src, (const int4*)dst);
    k_epi    <<<dim3(NH/64, V*T), 256>>>(Wp, Bp, out);
}

// round 9
// speedup vs baseline: 1.5840x; 1.0364x over previous
#include <cuda_runtime.h>
#include <cuda_fp16.h>
#include <math.h>

// Problem constants (fixed shapes per reference)
#define V  4
#define T  4
#define NS 100000
#define NH 12288
#define E  100000
#define H  64
#define C  (V*T)          // 16 (v, t') edge-type combos
#define NEG 0.01f

// ---------------- scratch (__device__ globals; no allocation allowed) ----------------
__device__ unsigned g_deg_out_p[C*NS/4];  // packed u8 out-degree (4 nodes / word)  1.6 MB
__device__ int      g_deg_in  [C*NH];     // in-degree per (combo, dst-node)        0.8 MB
__device__ uint2    g_xnh     [C*NS];     // half4 normalized feats per combo      12.8 MB
__device__ float4   g_s4      [C*NH];     // s accumulators, t in components        3.0 MB

__device__ __forceinline__ float fixnum(float a) {
    if (isnan(a)) return 0.0f;
    if (isinf(a)) return a > 0.0f ? 3.4028234663852886e38f : -3.4028234663852886e38f;
    return a;
}

__device__ __forceinline__ void red_add_v4(float4* addr, float a, float b, float c, float d) {
    asm volatile("red.global.add.v4.f32 [%0], {%1, %2, %3, %4};"
                 :: "l"(addr), "f"(a), "f"(b), "f"(c), "f"(d) : "memory");
}

// ---- packed f32x2 helpers (Blackwell FFMA2) ----
__device__ __forceinline__ unsigned long long pk2(float a, float b) {
    unsigned long long r;
    asm("mov.b64 %0, {%1, %2};" : "=l"(r) : "f"(a), "f"(b));
    return r;
}
__device__ __forceinline__ void upk2(unsigned long long v, float& a, float& b) {
    asm("mov.b64 {%0, %1}, %2;" : "=f"(a), "=f"(b) : "l"(v));
}
__device__ __forceinline__ unsigned long long fma2(unsigned long long a,
                                                   unsigned long long b,
                                                   unsigned long long c) {
    unsigned long long r;
    asm("fma.rn.f32x2 %0, %1, %2, %3;" : "=l"(r) : "l"(a), "l"(b), "l"(c));
    return r;
}

// ---------------- K1: zero all accumulators (grid-stride, 16B stores) ----------------
__global__ void k_init() {
    int tid0   = blockIdx.x * blockDim.x + threadIdx.x;
    int stride = gridDim.x * blockDim.x;
    const int4   z4 = make_int4(0, 0, 0, 0);
    const float4 zf = make_float4(0.f, 0.f, 0.f, 0.f);
    for (int j = tid0; j < C*NS/16; j += stride)           // 1.6 MB packed deg_out
        reinterpret_cast<int4*>(g_deg_out_p)[j] = z4;
    for (int j = tid0; j < C*NH/4; j += stride)            // deg_in
        reinterpret_cast<int4*>(g_deg_in)[j] = z4;
    for (int j = tid0; j < C*NH; j += stride)              // s accumulators
        g_s4[j] = zf;
}

// ---------------- K2: degree counts ----------------
// deg_out packed: 4 u8 counters per word (max out-degree ~12 << 255, safe).
// thread = 4 consecutive edges of one combo (E % 4 == 0, quads never straddle combos)
__global__ void k_deg(const int4* __restrict__ src4, const int4* __restrict__ dst4) {
    int i = blockIdx.x * blockDim.x + threadIdx.x;
    if (i >= C*E/4) return;
    int c = i / (E/4);
    int4 s = src4[i];
    int4 d = dst4[i];
    unsigned* dout = g_deg_out_p + c*(NS/4);
    int*      din  = g_deg_in    + c*NH;
    atomicAdd(&dout[s.x >> 2], 1u << ((s.x & 3) << 3));
    atomicAdd(&dout[s.y >> 2], 1u << ((s.y & 3) << 3));
    atomicAdd(&dout[s.z >> 2], 1u << ((s.z & 3) << 3));
    atomicAdd(&dout[s.w >> 2], 1u << ((s.w & 3) << 3));
    atomicAdd(&din[d.x], 1); atomicAdd(&din[d.y], 1);
    atomicAdd(&din[d.z], 1); atomicAdd(&din[d.w], 1);
}

// ---------------- K3: build normalized half4 features ----------------
// xn[c][s] = half4( fix(x[v,:,s]) * rsqrt(max(deg_out[c][s],1)) )  — fully coalesced
__global__ void k_xn(const float* __restrict__ x) {
    int i = blockIdx.x * blockDim.x + threadIdx.x;
    if (i >= C*NS) return;
    int c = i / NS, s = i - c*NS;
    int v = c >> 2;
    unsigned w = g_deg_out_p[c*(NS/4) + (s >> 2)];
    int deg = (w >> ((s & 3) << 3)) & 255;
    float nrm = rsqrtf(fmaxf((float)deg, 1.0f));
    float2 lo = make_float2(fixnum(x[(v*T + 0)*NS + s]) * nrm,
                            fixnum(x[(v*T + 1)*NS + s]) * nrm);
    float2 hi = make_float2(fixnum(x[(v*T + 2)*NS + s]) * nrm,
                            fixnum(x[(v*T + 3)*NS + s]) * nrm);
    __half2 h0 = __float22half2_rn(lo);
    __half2 h1 = __float22half2_rn(hi);
    uint2 e;
    e.x = *reinterpret_cast<unsigned*>(&h0);
    e.y = *reinterpret_cast<unsigned*>(&h1);
    g_xnh[i] = e;
}

// ---------------- K4: scatter — one 8B gather + one v4 RED per edge ----------------
__global__ void __launch_bounds__(256) k_scatter(const int4* __restrict__ src4,
                                                 const int4* __restrict__ dst4) {
    int i = blockIdx.x * blockDim.x + threadIdx.x;
    if (i >= C*E/4) return;
    int c = i / (E/4);
    int4 sq = src4[i];
    int4 dq = dst4[i];

    const uint2* __restrict__ xn = g_xnh + c*NS;
    float4*                   sc = g_s4  + c*NH;

    // issue all 4 gathers first (independent chains -> MLP=4)
    uint2 q0 = xn[sq.x];
    uint2 q1 = xn[sq.y];
    uint2 q2 = xn[sq.z];
    uint2 q3 = xn[sq.w];

#pragma unroll
    for (int k = 0; k < 4; k++) {
        uint2 q = (k == 0) ? q0 : (k == 1) ? q1 : (k == 2) ? q2 : q3;
        int   d = (k == 0) ? dq.x : (k == 1) ? dq.y : (k == 2) ? dq.z : dq.w;
        float2 f0 = __half22float2(*reinterpret_cast<__half2*>(&q.x));
        float2 f1 = __half22float2(*reinterpret_cast<__half2*>(&q.y));
        red_add_v4(&sc[d], f0.x, f0.y, f1.x, f1.y);
    }
}

// ---------------- K5: epilogue  out[nh,v,t,h] = sum_{t'} lrelu(s*norm_dst*W + b) ----------------
// grid: (NH/64, V*T), block 256. Packed f32x2 math; lrelu(y) = c1*y + c2*|y|.
__global__ void __launch_bounds__(256) k_epi(const float* __restrict__ Wp,
                                             const float* __restrict__ Bp,
                                             float* __restrict__ out) {
    int vt = blockIdx.y;            // v*T + t
    int v  = vt >> 2;
    int t  = vt & 3;
    int tid = threadIdx.x;

    __shared__ float sW[T*H];       // [t'][h]
    __shared__ float sB[T*H];
    __shared__ float ss[T*64];      // [t'][nh_local], norm_dst folded
    sW[tid] = Wp[v*(T*H) + tid];
    sB[tid] = Bp[v*(T*H) + tid];
    {
        int tp = tid >> 6;          // 0..3 (edge type t')
        int nl = tid & 63;
        int nh = blockIdx.x*64 + nl;
        int cc = v*T + tp;
        float nd = rsqrtf(fmaxf((float)g_deg_in[cc*NH + nh], 1.0f));
        ss[tid] = reinterpret_cast<const float*>(g_s4 + (cc*NH + nh))[t] * nd;
    }
    __syncthreads();

    int hq  = tid & 15;             // h-quad: h = hq*4 .. hq*4+3
    int row = tid >> 4;             // 0..15

    // hoist W/B pairs into packed regs: [p][kk] kk=0 -> (h0,h1), kk=1 -> (h2,h3)
    unsigned long long wr2[8], br2[8];
#pragma unroll
    for (int p = 0; p < 4; p++)
#pragma unroll
        for (int kk = 0; kk < 2; kk++) {
            int h = hq*4 + kk*2;
            wr2[p*2 + kk] = pk2(sW[p*H + h], sW[p*H + h + 1]);
            br2[p*2 + kk] = pk2(sB[p*H + h], sB[p*H + h + 1]);
        }

    const float c1f = 0.5f * (1.0f + NEG);
    const float c2f = 0.5f * (1.0f - NEG);
    const unsigned long long C1 = pk2(c1f, c1f);
    const unsigned long long C2 = pk2(c2f, c2f);
    const unsigned long long ABSM = 0x7FFFFFFF7FFFFFFFull;

#pragma unroll
    for (int j = 0; j < 4; j++) {
        int nl = row + 16*j;
        int nh = blockIdx.x*64 + nl;
        unsigned long long a0 = 0ull, a1 = 0ull;   // packed zero accumulators
#pragma unroll
        for (int p = 0; p < 4; p++) {
            float sv = ss[p*64 + nl];
            unsigned long long sv2 = pk2(sv, sv);
            unsigned long long y0 = fma2(sv2, wr2[p*2 + 0], br2[p*2 + 0]);
            unsigned long long y1 = fma2(sv2, wr2[p*2 + 1], br2[p*2 + 1]);
            a0 = fma2(y0, C1, a0);
            a0 = fma2(y0 & ABSM, C2, a0);
            a1 = fma2(y1, C1, a1);
            a1 = fma2(y1 & ABSM, C2, a1);
        }
        float4 acc;
        upk2(a0, acc.x, acc.y);
        upk2(a1, acc.z, acc.w);
        // out index: ((nh*V + v)*T + t)*H + hq*4  -> float4 slot (nh*16 + vt)*16 + hq
        reinterpret_cast<float4*>(out)[(nh*16 + vt)*16 + hq] = acc;
    }
}

// ---------------- launcher ----------------
extern "C" void kernel_launch(void* const* d_in, const int* in_sizes, int n_in,
                              void* d_out, int out_size) {
    const float* x   = (const float*)d_in[0];   // [V,T,NS]
    const float* Wp  = (const float*)d_in[1];   // [V,T,H]
    const float* Bp  = (const float*)d_in[2];   // [V,T,H]
    const int*   src = (const int*)  d_in[3];   // [V,T,E]
    const int*   dst = (const int*)  d_in[4];   // [V,T,E]
    float* out = (float*)d_out;                 // [NH,V,T,H]
    (void)in_sizes; (void)n_in; (void)out_size;

    const int QUADS = C*E/4;                    // 400,000

    k_init   <<<592, 256>>>();
    k_deg    <<<(QUADS + 255)/256, 256>>>((const int4*)src, (const int4*)dst);
    k_xn     <<<(C*NS + 255)/256, 256>>>(x);
    k_scatter<<<(QUADS + 255)/256, 256>>>((const int4*)src, (const int4*)dst);
    k_epi    <<<dim3(NH/64, V*T), 256>>>(Wp, Bp, out);
}

// round 10
// speedup vs baseline: 1.6571x; 1.0461x over previous
#include <cuda_runtime.h>
#include <cuda_fp16.h>
#include <math.h>

// Problem constants (fixed shapes per reference)
#define V  4
#define T  4
#define NS 100000
#define NH 12288
#define E  100000
#define H  64
#define C  (V*T)          // 16 (v, t') edge-type combos
#define NEG 0.01f

// ---------------- scratch (__device__ globals; no allocation allowed) ----------------
__device__ unsigned g_deg_out_p[C*NS/4];  // packed u8 out-degree (4 nodes / word)  1.6 MB
__device__ int      g_deg_in  [C*NH];     // in-degree per (combo, dst-node)        0.8 MB
__device__ uint2    g_xnh     [C*NS];     // half4 normalized feats per combo      12.8 MB
__device__ float4   g_s4      [C*NH];     // s accumulators, t in components        3.0 MB

__device__ __forceinline__ float fixnum(float a) {
    if (isnan(a)) return 0.0f;
    if (isinf(a)) return a > 0.0f ? 3.4028234663852886e38f : -3.4028234663852886e38f;
    return a;
}

__device__ __forceinline__ void red_add_v4(float4* addr, float a, float b, float c, float d) {
    asm volatile("red.global.add.v4.f32 [%0], {%1, %2, %3, %4};"
                 :: "l"(addr), "f"(a), "f"(b), "f"(c), "f"(d) : "memory");
}

// ---- packed f32x2 helpers (Blackwell FFMA2) ----
__device__ __forceinline__ unsigned long long pk2(float a, float b) {
    unsigned long long r;
    asm("mov.b64 %0, {%1, %2};" : "=l"(r) : "f"(a), "f"(b));
    return r;
}
__device__ __forceinline__ void upk2(unsigned long long v, float& a, float& b) {
    asm("mov.b64 {%0, %1}, %2;" : "=f"(a), "=f"(b) : "l"(v));
}
__device__ __forceinline__ unsigned long long fma2(unsigned long long a,
                                                   unsigned long long b,
                                                   unsigned long long c) {
    unsigned long long r;
    asm("fma.rn.f32x2 %0, %1, %2, %3;" : "=l"(r) : "l"(a), "l"(b), "l"(c));
    return r;
}

// ---------------- K1: zero all accumulators (grid-stride, 16B stores) ----------------
__global__ void k_init() {
    int tid0   = blockIdx.x * blockDim.x + threadIdx.x;
    int stride = gridDim.x * blockDim.x;
    const int4   z4 = make_int4(0, 0, 0, 0);
    const float4 zf = make_float4(0.f, 0.f, 0.f, 0.f);
    for (int j = tid0; j < C*NS/16; j += stride)           // packed deg_out
        reinterpret_cast<int4*>(g_deg_out_p)[j] = z4;
    for (int j = tid0; j < C*NH/4; j += stride)            // deg_in
        reinterpret_cast<int4*>(g_deg_in)[j] = z4;
    for (int j = tid0; j < C*NH; j += stride)              // s accumulators
        g_s4[j] = zf;
    cudaTriggerProgrammaticLaunchCompletion();
}

// ---------------- K2: degree counts (8 edges/thread) ----------------
// deg_out packed: 4 u8 counters per word (max out-degree ~12 << 255, safe).
// E % 8 == 0, so 8-edge groups never straddle combos.
__global__ void __launch_bounds__(256) k_deg(const int4* __restrict__ src4,
                                             const int4* __restrict__ dst4) {
    int i = blockIdx.x * blockDim.x + threadIdx.x;
    if (i >= C*E/8) return;
    int c = i / (E/8);
    // prologue: independent edge-list loads (before the PDL dependency sync)
    int4 s0 = src4[2*i],   s1 = src4[2*i + 1];
    int4 d0 = dst4[2*i],   d1 = dst4[2*i + 1];
    cudaGridDependencySynchronize();        // counters zeroed by k_init
    unsigned* dout = g_deg_out_p + c*(NS/4);
    int*      din  = g_deg_in    + c*NH;
    int sv[8] = {s0.x, s0.y, s0.z, s0.w, s1.x, s1.y, s1.z, s1.w};
    int dv[8] = {d0.x, d0.y, d0.z, d0.w, d1.x, d1.y, d1.z, d1.w};
#pragma unroll
    for (int k = 0; k < 8; k++) {
        atomicAdd(&dout[sv[k] >> 2], 1u << ((sv[k] & 3) << 3));
        atomicAdd(&din[dv[k]], 1);
    }
    cudaTriggerProgrammaticLaunchCompletion();
}

// ---------------- K3: build normalized half4 features ----------------
// thread = (v, s): reads x once, writes all 4 combos of this v.
__global__ void k_xn(const float* __restrict__ x) {
    int i = blockIdx.x * blockDim.x + threadIdx.x;
    if (i >= V*NS) return;
    int v = i / NS, s = i - v*NS;
    // prologue: independent x loads
    float4 xv;
    xv.x = fixnum(x[(v*T + 0)*NS + s]);
    xv.y = fixnum(x[(v*T + 1)*NS + s]);
    xv.z = fixnum(x[(v*T + 2)*NS + s]);
    xv.w = fixnum(x[(v*T + 3)*NS + s]);
    cudaGridDependencySynchronize();        // deg_out final after k_deg
#pragma unroll
    for (int tp = 0; tp < 4; tp++) {
        int c = v*4 + tp;
        unsigned w = g_deg_out_p[c*(NS/4) + (s >> 2)];
        int deg = (w >> ((s & 3) << 3)) & 255;
        float nrm = rsqrtf(fmaxf((float)deg, 1.0f));
        __half2 h0 = __floats2half2_rn(xv.x * nrm, xv.y * nrm);
        __half2 h1 = __floats2half2_rn(xv.z * nrm, xv.w * nrm);
        uint2 e;
        e.x = *reinterpret_cast<unsigned*>(&h0);
        e.y = *reinterpret_cast<unsigned*>(&h1);
        g_xnh[c*NS + s] = e;
    }
    cudaTriggerProgrammaticLaunchCompletion();
}

// ---------------- K4: scatter — 8 edges/thread, one 8B gather + one v4 RED per edge ----------------
__global__ void __launch_bounds__(256) k_scatter(const int4* __restrict__ src4,
                                                 const int4* __restrict__ dst4) {
    int i = blockIdx.x * blockDim.x + threadIdx.x;
    if (i >= C*E/8) return;
    int c = i / (E/8);
    // prologue: independent edge-list loads
    int4 sa = src4[2*i],   sb = src4[2*i + 1];
    int4 da = dst4[2*i],   db = dst4[2*i + 1];
    cudaGridDependencySynchronize();        // g_xnh ready (k_xn), g_s4 zeroed (k_init)

    const uint2* __restrict__ xn = g_xnh + c*NS;
    float4*                   sc = g_s4  + c*NH;

    int sv[8] = {sa.x, sa.y, sa.z, sa.w, sb.x, sb.y, sb.z, sb.w};
    int dv[8] = {da.x, da.y, da.z, da.w, db.x, db.y, db.z, db.w};

    // issue all 8 gathers first (independent chains -> MLP=8)
    uint2 q[8];
#pragma unroll
    for (int k = 0; k < 8; k++) q[k] = xn[sv[k]];
#pragma unroll
    for (int k = 0; k < 8; k++) {
        float2 f0 = __half22float2(*reinterpret_cast<__half2*>(&q[k].x));
        float2 f1 = __half22float2(*reinterpret_cast<__half2*>(&q[k].y));
        red_add_v4(&sc[dv[k]], f0.x, f0.y, f1.x, f1.y);
    }
    cudaTriggerProgrammaticLaunchCompletion();
}

// ---------------- K5: epilogue  out[nh,v,t,h] = sum_{t'} lrelu(s*norm_dst*W + b) ----------------
// grid: (NH/64, V*T), block 256. Packed f32x2 math; lrelu(y) = c1*y + c2*|y|.
__global__ void __launch_bounds__(256) k_epi(const float* __restrict__ Wp,
                                             const float* __restrict__ Bp,
                                             float* __restrict__ out) {
    int vt = blockIdx.y;            // v*T + t
    int v  = vt >> 2;
    int t  = vt & 3;
    int tid = threadIdx.x;

    __shared__ float sW[T*H];       // [t'][h]
    __shared__ float sB[T*H];
    __shared__ float ss[T*64];      // [t'][nh_local], norm_dst folded
    // prologue: independent W/B loads
    sW[tid] = Wp[v*(T*H) + tid];
    sB[tid] = Bp[v*(T*H) + tid];
    cudaGridDependencySynchronize();        // g_s4 / deg_in final
    {
        int tp = tid >> 6;          // 0..3 (edge type t')
        int nl = tid & 63;
        int nh = blockIdx.x*64 + nl;
        int cc = v*T + tp;
        float nd = rsqrtf(fmaxf((float)g_deg_in[cc*NH + nh], 1.0f));
        ss[tid] = reinterpret_cast<const float*>(g_s4 + (cc*NH + nh))[t] * nd;
    }
    __syncthreads();

    int hq  = tid & 15;             // h-quad: h = hq*4 .. hq*4+3
    int row = tid >> 4;             // 0..15

    // hoist W/B pairs into packed regs: [p][kk] kk=0 -> (h0,h1), kk=1 -> (h2,h3)
    unsigned long long wr2[8], br2[8];
#pragma unroll
    for (int p = 0; p < 4; p++)
#pragma unroll
        for (int kk = 0; kk < 2; kk++) {
            int h = hq*4 + kk*2;
            wr2[p*2 + kk] = pk2(sW[p*H + h], sW[p*H + h + 1]);
            br2[p*2 + kk] = pk2(sB[p*H + h], sB[p*H + h + 1]);
        }

    const float c1f = 0.5f * (1.0f + NEG);
    const float c2f = 0.5f * (1.0f - NEG);
    const unsigned long long C1 = pk2(c1f, c1f);
    const unsigned long long C2 = pk2(c2f, c2f);
    const unsigned long long ABSM = 0x7FFFFFFF7FFFFFFFull;

#pragma unroll
    for (int j = 0; j < 4; j++) {
        int nl = row + 16*j;
        int nh = blockIdx.x*64 + nl;
        unsigned long long a0 = 0ull, a1 = 0ull;   // packed zero accumulators
#pragma unroll
        for (int p = 0; p < 4; p++) {
            float sv = ss[p*64 + nl];
            unsigned long long sv2 = pk2(sv, sv);
            unsigned long long y0 = fma2(sv2, wr2[p*2 + 0], br2[p*2 + 0]);
            unsigned long long y1 = fma2(sv2, wr2[p*2 + 1], br2[p*2 + 1]);
            a0 = fma2(y0, C1, a0);
            a0 = fma2(y0 & ABSM, C2, a0);
            a1 = fma2(y1, C1, a1);
            a1 = fma2(y1 & ABSM, C2, a1);
        }
        float4 acc;
        upk2(a0, acc.x, acc.y);
        upk2(a1, acc.z, acc.w);
        // out index: ((nh*V + v)*T + t)*H + hq*4  -> float4 slot (nh*16 + vt)*16 + hq
        reinterpret_cast<float4*>(out)[(nh*16 + vt)*16 + hq] = acc;
    }
}

// ---------------- PDL launch helper ----------------
template <typename F, typename... Args>
static inline void launch_pdl(F* k, dim3 grid, dim3 block, Args... args) {
    cudaLaunchConfig_t cfg = {};
    cfg.gridDim = grid;
    cfg.blockDim = block;
    cfg.dynamicSmemBytes = 0;
    cfg.stream = 0;
    cudaLaunchAttribute at[1];
    at[0].id = cudaLaunchAttributeProgrammaticStreamSerialization;
    at[0].val.programmaticStreamSerializationAllowed = 1;
    cfg.attrs = at;
    cfg.numAttrs = 1;
    cudaLaunchKernelEx(&cfg, k, args...);
}

// ---------------- launcher ----------------
extern "C" void kernel_launch(void* const* d_in, const int* in_sizes, int n_in,
                              void* d_out, int out_size) {
    const float* x   = (const float*)d_in[0];   // [V,T,NS]
    const float* Wp  = (const float*)d_in[1];   // [V,T,H]
    const float* Bp  = (const float*)d_in[2];   // [V,T,H]
    const int*   src = (const int*)  d_in[3];   // [V,T,E]
    const int*   dst = (const int*)  d_in[4];   // [V,T,E]
    float* out = (float*)d_out;                 // [NH,V,T,H]
    (void)in_sizes; (void)n_in; (void)out_size;

    const int OCT = C*E/8;                      // 200,000 8-edge groups

    k_init<<<592, 256>>>();
    launch_pdl(k_deg,     dim3((OCT + 255)/256),      dim3(256),
               (const int4*)src, (const int4*)dst);
    launch_pdl(k_xn,      dim3((V*NS + 255)/256),     dim3(256), x);
    launch_pdl(k_scatter, dim3((OCT + 255)/256),      dim3(256),
               (const int4*)src, (const int4*)dst);
    launch_pdl(k_epi,     dim3(NH/64, V*T),           dim3(256), Wp, Bp, out);
}

// round 11
// speedup vs baseline: 1.7692x; 1.0677x over previous
#include <cuda_runtime.h>
#include <cuda_fp16.h>
#include <math.h>

// Problem constants (fixed shapes per reference)
#define V  4
#define T  4
#define NS 100000
#define NH 12288
#define E  100000
#define H  64
#define C  (V*T)          // 16 (v, t') edge-type combos
#define NEG 0.01f

// ---------------- scratch (__device__ globals; no allocation allowed) ----------------
__device__ unsigned g_deg_out_p[C*NS/4];  // packed u8 out-degree (4 nodes / word)  1.6 MB
__device__ int      g_deg_in  [C*NH];     // in-degree per (combo, dst-node)        0.8 MB
__device__ uint2    g_xnh     [C*NS];     // half4 normalized feats per combo      12.8 MB
__device__ float4   g_s4      [C*NH];     // s accumulators, t in components        3.0 MB

__device__ __forceinline__ float fixnum(float a) {
    if (isnan(a)) return 0.0f;
    if (isinf(a)) return a > 0.0f ? 3.4028234663852886e38f : -3.4028234663852886e38f;
    return a;
}

__device__ __forceinline__ void red_add_v4(float4* addr, float a, float b, float c, float d) {
    asm volatile("red.global.add.v4.f32 [%0], {%1, %2, %3, %4};"
                 :: "l"(addr), "f"(a), "f"(b), "f"(c), "f"(d) : "memory");
}

// ---- packed f32x2 helpers (Blackwell FFMA2) ----
__device__ __forceinline__ unsigned long long pk2(float a, float b) {
    unsigned long long r;
    asm("mov.b64 %0, {%1, %2};" : "=l"(r) : "f"(a), "f"(b));
    return r;
}
__device__ __forceinline__ void upk2(unsigned long long v, float& a, float& b) {
    asm("mov.b64 {%0, %1}, %2;" : "=f"(a), "=f"(b) : "l"(v));
}
__device__ __forceinline__ unsigned long long fma2(unsigned long long a,
                                                   unsigned long long b,
                                                   unsigned long long c) {
    unsigned long long r;
    asm("fma.rn.f32x2 %0, %1, %2, %3;" : "=l"(r) : "l"(a), "l"(b), "l"(c));
    return r;
}

// ---------------- K1: zero all accumulators (grid-stride, 16B stores) ----------------
__global__ void k_init() {
    int tid0   = blockIdx.x * blockDim.x + threadIdx.x;
    int stride = gridDim.x * blockDim.x;
    const int4   z4 = make_int4(0, 0, 0, 0);
    const float4 zf = make_float4(0.f, 0.f, 0.f, 0.f);
    for (int j = tid0; j < C*NS/16; j += stride)           // packed deg_out
        reinterpret_cast<int4*>(g_deg_out_p)[j] = z4;
    for (int j = tid0; j < C*NH/4; j += stride)            // deg_in
        reinterpret_cast<int4*>(g_deg_in)[j] = z4;
    for (int j = tid0; j < C*NH; j += stride)              // s accumulators
        g_s4[j] = zf;
    cudaTriggerProgrammaticLaunchCompletion();
}

// ---------------- K2: degree counts (4 edges/thread) ----------------
// deg_out packed: 4 u8 counters per word (max out-degree ~12 << 255, safe).
// thread = 4 consecutive edges of one combo (E % 4 == 0, quads never straddle combos)
__global__ void __launch_bounds__(256, 8) k_deg(const int4* __restrict__ src4,
                                                const int4* __restrict__ dst4) {
    int i = blockIdx.x * blockDim.x + threadIdx.x;
    if (i >= C*E/4) return;
    int c = i / (E/4);
    // prologue: independent edge-list loads (before the PDL dependency sync)
    int4 s = src4[i];
    int4 d = dst4[i];
    cudaGridDependencySynchronize();        // counters zeroed by k_init
    unsigned* dout = g_deg_out_p + c*(NS/4);
    int*      din  = g_deg_in    + c*NH;
    atomicAdd(&dout[s.x >> 2], 1u << ((s.x & 3) << 3));
    atomicAdd(&dout[s.y >> 2], 1u << ((s.y & 3) << 3));
    atomicAdd(&dout[s.z >> 2], 1u << ((s.z & 3) << 3));
    atomicAdd(&dout[s.w >> 2], 1u << ((s.w & 3) << 3));
    atomicAdd(&din[d.x], 1); atomicAdd(&din[d.y], 1);
    atomicAdd(&din[d.z], 1); atomicAdd(&din[d.w], 1);
    cudaTriggerProgrammaticLaunchCompletion();
}

// ---------------- K3: build normalized half4 features ----------------
// thread = (v, s): reads x once, writes all 4 combos of this v.
__global__ void k_xn(const float* __restrict__ x) {
    int i = blockIdx.x * blockDim.x + threadIdx.x;
    if (i >= V*NS) return;
    int v = i / NS, s = i - v*NS;
    // prologue: independent x loads
    float4 xv;
    xv.x = fixnum(x[(v*T + 0)*NS + s]);
    xv.y = fixnum(x[(v*T + 1)*NS + s]);
    xv.z = fixnum(x[(v*T + 2)*NS + s]);
    xv.w = fixnum(x[(v*T + 3)*NS + s]);
    cudaGridDependencySynchronize();        // deg_out final after k_deg
#pragma unroll
    for (int tp = 0; tp < 4; tp++) {
        int c = v*4 + tp;
        unsigned w = g_deg_out_p[c*(NS/4) + (s >> 2)];
        int deg = (w >> ((s & 3) << 3)) & 255;
        float nrm = rsqrtf(fmaxf((float)deg, 1.0f));
        __half2 h0 = __floats2half2_rn(xv.x * nrm, xv.y * nrm);
        __half2 h1 = __floats2half2_rn(xv.z * nrm, xv.w * nrm);
        uint2 e;
        e.x = *reinterpret_cast<unsigned*>(&h0);
        e.y = *reinterpret_cast<unsigned*>(&h1);
        g_xnh[c*NS + s] = e;
    }
    cudaTriggerProgrammaticLaunchCompletion();
}

// ---------------- K4: scatter — 4 edges/thread, one 8B gather + one v4 RED per edge ----------------
__global__ void __launch_bounds__(256, 8) k_scatter(const int4* __restrict__ src4,
                                                    const int4* __restrict__ dst4) {
    int i = blockIdx.x * blockDim.x + threadIdx.x;
    if (i >= C*E/4) return;
    int c = i / (E/4);
    // prologue: independent edge-list loads
    int4 sq = src4[i];
    int4 dq = dst4[i];
    cudaGridDependencySynchronize();        // g_xnh ready (k_xn), g_s4 zeroed (k_init)

    const uint2* __restrict__ xn = g_xnh + c*NS;
    float4*                   sc = g_s4  + c*NH;

    // issue all 4 gathers first (independent chains -> MLP=4)
    uint2 q0 = xn[sq.x];
    uint2 q1 = xn[sq.y];
    uint2 q2 = xn[sq.z];
    uint2 q3 = xn[sq.w];

#pragma unroll
    for (int k = 0; k < 4; k++) {
        uint2 q = (k == 0) ? q0 : (k == 1) ? q1 : (k == 2) ? q2 : q3;
        int   d = (k == 0) ? dq.x : (k == 1) ? dq.y : (k == 2) ? dq.z : dq.w;
        float2 f0 = __half22float2(*reinterpret_cast<__half2*>(&q.x));
        float2 f1 = __half22float2(*reinterpret_cast<__half2*>(&q.y));
        red_add_v4(&sc[d], f0.x, f0.y, f1.x, f1.y);
    }
    cudaTriggerProgrammaticLaunchCompletion();
}

// ---------------- K5: epilogue  out[nh,v,t,h] = sum_{t'} lrelu(s*norm_dst*W + b) ----------------
// grid: (NH/64, V*T), block 256. Packed f32x2 math; lrelu(y) = c1*y + c2*|y|.
__global__ void __launch_bounds__(256) k_epi(const float* __restrict__ Wp,
                                             const float* __restrict__ Bp,
                                             float* __restrict__ out) {
    int vt = blockIdx.y;            // v*T + t
    int v  = vt >> 2;
    int t  = vt & 3;
    int tid = threadIdx.x;

    __shared__ float sW[T*H];       // [t'][h]
    __shared__ float sB[T*H];
    __shared__ float ss[T*64];      // [t'][nh_local], norm_dst folded
    // prologue: independent W/B loads
    sW[tid] = Wp[v*(T*H) + tid];
    sB[tid] = Bp[v*(T*H) + tid];
    cudaGridDependencySynchronize();        // g_s4 / deg_in final
    {
        int tp = tid >> 6;          // 0..3 (edge type t')
        int nl = tid & 63;
        int nh = blockIdx.x*64 + nl;
        int cc = v*T + tp;
        float nd = rsqrtf(fmaxf((float)g_deg_in[cc*NH + nh], 1.0f));
        ss[tid] = reinterpret_cast<const float*>(g_s4 + (cc*NH + nh))[t] * nd;
    }
    __syncthreads();

    int hq  = tid & 15;             // h-quad: h = hq*4 .. hq*4+3
    int row = tid >> 4;             // 0..15

    // hoist W/B pairs into packed regs: [p][kk] kk=0 -> (h0,h1), kk=1 -> (h2,h3)
    unsigned long long wr2[8], br2[8];
#pragma unroll
    for (int p = 0; p < 4; p++)
#pragma unroll
        for (int kk = 0; kk < 2; kk++) {
            int h = hq*4 + kk*2;
            wr2[p*2 + kk] = pk2(sW[p*H + h], sW[p*H + h + 1]);
            br2[p*2 + kk] = pk2(sB[p*H + h], sB[p*H + h + 1]);
        }

    const float c1f = 0.5f * (1.0f + NEG);
    const float c2f = 0.5f * (1.0f - NEG);
    const unsigned long long C1 = pk2(c1f, c1f);
    const unsigned long long C2 = pk2(c2f, c2f);
    const unsigned long long ABSM = 0x7FFFFFFF7FFFFFFFull;

#pragma unroll
    for (int j = 0; j < 4; j++) {
        int nl = row + 16*j;
        int nh = blockIdx.x*64 + nl;
        unsigned long long a0 = 0ull, a1 = 0ull;   // packed zero accumulators
#pragma unroll
        for (int p = 0; p < 4; p++) {
            float sv = ss[p*64 + nl];
            unsigned long long sv2 = pk2(sv, sv);
            unsigned long long y0 = fma2(sv2, wr2[p*2 + 0], br2[p*2 + 0]);
            unsigned long long y1 = fma2(sv2, wr2[p*2 + 1], br2[p*2 + 1]);
            a0 = fma2(y0, C1, a0);
            a0 = fma2(y0 & ABSM, C2, a0);
            a1 = fma2(y1, C1, a1);
            a1 = fma2(y1 & ABSM, C2, a1);
        }
        float4 acc;
        upk2(a0, acc.x, acc.y);
        upk2(a1, acc.z, acc.w);
        // out index: ((nh*V + v)*T + t)*H + hq*4  -> float4 slot (nh*16 + vt)*16 + hq
        reinterpret_cast<float4*>(out)[(nh*16 + vt)*16 + hq] = acc;
    }
}

// ---------------- PDL launch helper ----------------
template <typename F, typename... Args>
static inline void launch_pdl(F* k, dim3 grid, dim3 block, Args... args) {
    cudaLaunchConfig_t cfg = {};
    cfg.gridDim = grid;
    cfg.blockDim = block;
    cfg.dynamicSmemBytes = 0;
    cfg.stream = 0;
    cudaLaunchAttribute at[1];
    at[0].id = cudaLaunchAttributeProgrammaticStreamSerialization;
    at[0].val.programmaticStreamSerializationAllowed = 1;
    cfg.attrs = at;
    cfg.numAttrs = 1;
    cudaLaunchKernelEx(&cfg, k, args...);
}

// ---------------- launcher ----------------
extern "C" void kernel_launch(void* const* d_in, const int* in_sizes, int n_in,
                              void* d_out, int out_size) {
    const float* x   = (const float*)d_in[0];   // [V,T,NS]
    const float* Wp  = (const float*)d_in[1];   // [V,T,H]
    const float* Bp  = (const float*)d_in[2];   // [V,T,H]
    const int*   src = (const int*)  d_in[3];   // [V,T,E]
    const int*   dst = (const int*)  d_in[4];   // [V,T,E]
    float* out = (float*)d_out;                 // [NH,V,T,H]
    (void)in_sizes; (void)n_in; (void)out_size;

    const int QUADS = C*E/4;                    // 400,000

    k_init<<<592, 256>>>();
    launch_pdl(k_deg,     dim3((QUADS + 255)/256),    dim3(256),
               (const int4*)src, (const int4*)dst);
    launch_pdl(k_xn,      dim3((V*NS + 255)/256),     dim3(256), x);
    launch_pdl(k_scatter, dim3((QUADS + 255)/256),    dim3(256),
               (const int4*)src, (const int4*)dst);
    launch_pdl(k_epi,     dim3(NH/64, V*T),           dim3(256), Wp, Bp, out);
}